// round 1
// baseline (speedup 1.0000x reference)
#include <cuda_runtime.h>

#define CIN   16
#define COUT  32
#define BATCH 8
#define MAXE  120000
#define MAXBLK 4096

// Scratch (static device globals; no allocation APIs).
__device__ float g_xt[(size_t)BATCH * MAXE * CIN];      // x transposed to [B][E][Cin]
__device__ float g_psum[MAXBLK * COUT];
__device__ float g_psq [MAXBLK * COUT];
__device__ float g_scale[COUT];
__device__ float g_shift[COUT];

// ---------- packed fp32x2 helpers (Blackwell FFMA2, full fp32 precision) ----------
__device__ __forceinline__ unsigned long long pack2(float lo, float hi) {
    unsigned long long r;
    asm("mov.b64 %0, {%1, %2};" : "=l"(r) : "f"(lo), "f"(hi));
    return r;
}
__device__ __forceinline__ void unpack2(unsigned long long v, float& lo, float& hi) {
    asm("mov.b64 {%0, %1}, %2;" : "=f"(lo), "=f"(hi) : "l"(v));
}
__device__ __forceinline__ unsigned long long ffma2(unsigned long long a,
                                                    unsigned long long b,
                                                    unsigned long long c) {
    unsigned long long d;
    asm("fma.rn.f32x2 %0, %1, %2, %3;" : "=l"(d) : "l"(a), "l"(b), "l"(c));
    return d;
}

__device__ __forceinline__ float getc(const float4& v, int i) {
    return i == 0 ? v.x : i == 1 ? v.y : i == 2 ? v.z : v.w;
}

// ---------- Kernel A: transpose x [B,Cin,E] -> g_xt [B,E,Cin] ----------
__global__ __launch_bounds__(256) void k_transpose(const float* __restrict__ x, int E) {
    __shared__ float tile[CIN][257];
    int b  = blockIdx.y;
    int t  = threadIdx.x;
    int e  = blockIdx.x * 256 + t;
    const float* xb = x + (size_t)b * CIN * E;
#pragma unroll
    for (int c = 0; c < CIN; c++)
        tile[c][t] = (e < E) ? xb[(size_t)c * E + e] : 0.0f;
    __syncthreads();
    if (e < E) {
        float4* dst = (float4*)(g_xt + ((size_t)b * E + e) * CIN);
#pragma unroll
        for (int q = 0; q < 4; q++)
            dst[q] = make_float4(tile[q * 4 + 0][t], tile[q * 4 + 1][t],
                                 tile[q * 4 + 2][t], tile[q * 4 + 3][t]);
    }
}

// ---------- Kernel B: mesh conv (2 edges/thread, f32x2) + BN partial stats ----------
__global__ __launch_bounds__(128) void k_conv(const int* __restrict__ gemm,
                                              const float* __restrict__ W,
                                              const float* __restrict__ bias,
                                              float* __restrict__ out, int E) {
    __shared__ __align__(16) unsigned long long sW[CIN * COUT * 5]; // [c][o][s], dup-packed
    __shared__ float sb[COUT];
    __shared__ float wsum[4][COUT];
    __shared__ float wsq[4][COUT];

    int t = threadIdx.x;
    for (int i = t; i < CIN * COUT * 5; i += 128) {
        int c = i / (COUT * 5);
        int r = i - c * (COUT * 5);
        int o = r / 5;
        int s = r - o * 5;
        float w = W[(o * CIN + c) * 5 + s];
        sW[i] = pack2(w, w);
    }
    if (t < COUT) sb[t] = bias[t];
    __syncthreads();

    int b   = blockIdx.y;
    int E2  = E >> 1;
    int pe  = blockIdx.x * 128 + t;
    bool valid = pe < E2;
    int pec = valid ? pe : 0;
    int e0  = pec * 2;
    int base = b * E;

    const int4* gv = (const int4*)gemm;
    int4 g0 = gv[base + e0];
    int4 g1 = gv[base + e0 + 1];

    const float4* xt4 = (const float4*)g_xt;
    const float4* X0 = xt4 + (size_t)(base + e0) * 4;
    const float4* X1 = X0 + 4;
    const float4* NA0 = xt4 + (size_t)(base + g0.x) * 4;
    const float4* NB0 = xt4 + (size_t)(base + g0.y) * 4;
    const float4* NC0 = xt4 + (size_t)(base + g0.z) * 4;
    const float4* ND0 = xt4 + (size_t)(base + g0.w) * 4;
    const float4* NA1 = xt4 + (size_t)(base + g1.x) * 4;
    const float4* NB1 = xt4 + (size_t)(base + g1.y) * 4;
    const float4* NC1 = xt4 + (size_t)(base + g1.z) * 4;
    const float4* ND1 = xt4 + (size_t)(base + g1.w) * 4;

    unsigned long long acc[COUT];
#pragma unroll
    for (int o = 0; o < COUT; o++) acc[o] = pack2(sb[o], sb[o]);

#pragma unroll
    for (int q = 0; q < 4; q++) {
        float4 x0 = X0[q], x1 = X1[q];
        float4 a0 = NA0[q], b0 = NB0[q], c0 = NC0[q], d0 = ND0[q];
        float4 a1 = NA1[q], b1 = NB1[q], c1 = NC1[q], d1 = ND1[q];
#pragma unroll
        for (int i = 0; i < 4; i++) {
            float aa0 = getc(a0, i), cc0 = getc(c0, i);
            float aa1 = getc(a1, i), cc1 = getc(c1, i);
            float bb0 = getc(b0, i), dd0 = getc(d0, i);
            float bb1 = getc(b1, i), dd1 = getc(d1, i);
            unsigned long long f[5];
            f[0] = pack2(getc(x0, i), getc(x1, i));
            f[1] = pack2(fabsf(aa0 - cc0), fabsf(aa1 - cc1));
            f[2] = pack2(aa0 + cc0, aa1 + cc1);
            f[3] = pack2(fabsf(bb0 - dd0), fabsf(bb1 - dd1));
            f[4] = pack2(bb0 + dd0, bb1 + dd1);
            int c = q * 4 + i;
            const ulonglong2* Wc = (const ulonglong2*)(sW + c * COUT * 5);
#pragma unroll
            for (int j = 0; j < (COUT * 5) / 2; j++) {   // 80 iters, LDS.128 each
                ulonglong2 w = Wc[j];
                const int fl0 = 2 * j, fl1 = 2 * j + 1;
                acc[fl0 / 5] = ffma2(f[fl0 % 5], w.x, acc[fl0 / 5]);
                acc[fl1 / 5] = ffma2(f[fl1 % 5], w.y, acc[fl1 / 5]);
            }
        }
    }

    // Write y and build per-thread channel stats.
    float ssum[COUT], ssq[COUT];
#pragma unroll
    for (int o = 0; o < COUT; o++) {
        float lo, hi;
        unpack2(acc[o], lo, hi);
        if (valid) {
            float2 st = make_float2(lo, hi);
            *(float2*)(out + ((size_t)b * COUT + o) * E + e0) = st;
        }
        ssum[o] = valid ? (lo + hi) : 0.0f;
        ssq[o]  = valid ? (lo * lo + hi * hi) : 0.0f;
    }

    // Warp transpose-reduce: lane l ends holding warp total for channel l.
    int lane = t & 31, wid = t >> 5;
#pragma unroll
    for (int m = 16; m >= 1; m >>= 1) {
        bool up = (lane & m) != 0;
#pragma unroll
        for (int i = 0; i < m; i++) {
            float ks = up ? ssum[i + m] : ssum[i];
            float ds = up ? ssum[i] : ssum[i + m];
            ssum[i] = ks + __shfl_xor_sync(0xffffffffu, ds, m);
            float kq = up ? ssq[i + m] : ssq[i];
            float dq = up ? ssq[i] : ssq[i + m];
            ssq[i] = kq + __shfl_xor_sync(0xffffffffu, dq, m);
        }
    }
    wsum[wid][lane] = ssum[0];
    wsq[wid][lane]  = ssq[0];
    __syncthreads();
    if (t < COUT) {
        float S = 0.0f, Q = 0.0f;
#pragma unroll
        for (int w2 = 0; w2 < 4; w2++) { S += wsum[w2][t]; Q += wsq[w2][t]; }
        int blk = blockIdx.y * gridDim.x + blockIdx.x;
        g_psum[blk * COUT + t] = S;
        g_psq [blk * COUT + t] = Q;
    }
}

// ---------- Kernel C: finalize BN stats -> per-channel scale/shift ----------
__global__ __launch_bounds__(256) void k_stats(const float* __restrict__ gamma,
                                               const float* __restrict__ beta,
                                               int nb, float invN) {
    __shared__ float sS[256], sQ[256];
    int ch = blockIdx.x;
    int t  = threadIdx.x;
    float S = 0.0f, Q = 0.0f;
    for (int i = t; i < nb; i += 256) {
        S += g_psum[i * COUT + ch];
        Q += g_psq [i * COUT + ch];
    }
    sS[t] = S; sQ[t] = Q;
    __syncthreads();
    for (int h = 128; h > 0; h >>= 1) {
        if (t < h) { sS[t] += sS[t + h]; sQ[t] += sQ[t + h]; }
        __syncthreads();
    }
    if (t == 0) {
        float mean = sS[0] * invN;
        float var  = sQ[0] * invN - mean * mean;
        float sc   = gamma[ch] * rsqrtf(var + 1e-5f);
        g_scale[ch] = sc;
        g_shift[ch] = beta[ch] - mean * sc;
    }
}

// ---------- Kernel D: normalize + ReLU in place on d_out ----------
__global__ __launch_bounds__(256) void k_norm(float* __restrict__ out, int E4) {
    int e4 = blockIdx.x * blockDim.x + threadIdx.x;
    if (e4 >= E4) return;
    int bo = blockIdx.y;              // b*COUT + o
    int ch = bo % COUT;
    float s  = g_scale[ch];
    float sh = g_shift[ch];
    float4* p = (float4*)out + (size_t)bo * E4 + e4;
    float4 v = *p;
    v.x = fmaxf(fmaf(v.x, s, sh), 0.0f);
    v.y = fmaxf(fmaf(v.y, s, sh), 0.0f);
    v.z = fmaxf(fmaf(v.z, s, sh), 0.0f);
    v.w = fmaxf(fmaf(v.w, s, sh), 0.0f);
    *p = v;
}

extern "C" void kernel_launch(void* const* d_in, const int* in_sizes, int n_in,
                              void* d_out, int out_size) {
    const float* x     = (const float*)d_in[0];
    const int*   gemm  = (const int*)  d_in[1];
    const float* W     = (const float*)d_in[2];
    const float* bias  = (const float*)d_in[3];
    const float* gamma = (const float*)d_in[4];
    const float* beta  = (const float*)d_in[5];
    float* out = (float*)d_out;

    int E  = in_sizes[0] / (BATCH * CIN);   // 120000
    int E2 = E >> 1;
    int E4 = E >> 2;

    dim3 gA((unsigned)((E + 255) / 256), BATCH);
    k_transpose<<<gA, 256>>>(x, E);

    dim3 gB((unsigned)((E2 + 127) / 128), BATCH);
    k_conv<<<gB, 128>>>(gemm, W, bias, out, E);

    int nb = (int)(gB.x * gB.y);
    k_stats<<<COUT, 256>>>(gamma, beta, nb, 1.0f / ((float)BATCH * (float)E));

    dim3 gD((unsigned)((E4 + 255) / 256), BATCH * COUT);
    k_norm<<<gD, 256>>>(out, E4);
}

// round 2
// speedup vs baseline: 1.0392x; 1.0392x over previous
#include <cuda_runtime.h>

#define CIN   16
#define COUT  32
#define BATCH 8
#define MAXE  120000
#define MAXBLK 8192

// Scratch (static device globals; no allocation APIs).
__device__ float g_xt[(size_t)BATCH * MAXE * CIN];      // x transposed to [B][E][Cin]
__device__ float g_psum[MAXBLK * COUT];
__device__ float g_psq [MAXBLK * COUT];
__device__ float g_scale[COUT];
__device__ float g_shift[COUT];

// ---------- packed fp32x2 helpers (full fp32 precision per lane) ----------
__device__ __forceinline__ unsigned long long pack2(float lo, float hi) {
    unsigned long long r;
    asm("mov.b64 %0, {%1, %2};" : "=l"(r) : "f"(lo), "f"(hi));
    return r;
}
__device__ __forceinline__ void unpack2(unsigned long long v, float& lo, float& hi) {
    asm("mov.b64 {%0, %1}, %2;" : "=f"(lo), "=f"(hi) : "l"(v));
}
__device__ __forceinline__ unsigned long long ffma2(unsigned long long a,
                                                    unsigned long long b,
                                                    unsigned long long c) {
    unsigned long long d;
    asm("fma.rn.f32x2 %0, %1, %2, %3;" : "=l"(d) : "l"(a), "l"(b), "l"(c));
    return d;
}

__device__ __forceinline__ float getc(const float4& v, int i) {
    return i == 0 ? v.x : i == 1 ? v.y : i == 2 ? v.z : v.w;
}

// ---------- Kernel A: transpose x [B,Cin,E] -> g_xt [B,E,Cin] ----------
__global__ __launch_bounds__(256) void k_transpose(const float* __restrict__ x, int E) {
    __shared__ float tile[CIN][257];
    int b  = blockIdx.y;
    int t  = threadIdx.x;
    int e  = blockIdx.x * 256 + t;
    const float* xb = x + (size_t)b * CIN * E;
#pragma unroll
    for (int c = 0; c < CIN; c++)
        tile[c][t] = (e < E) ? xb[(size_t)c * E + e] : 0.0f;
    __syncthreads();
    if (e < E) {
        float4* dst = (float4*)(g_xt + ((size_t)b * E + e) * CIN);
#pragma unroll
        for (int q = 0; q < 4; q++)
            dst[q] = make_float4(tile[q * 4 + 0][t], tile[q * 4 + 1][t],
                                 tile[q * 4 + 2][t], tile[q * 4 + 3][t]);
    }
}

// ---------- Kernel B: mesh conv, 1 edge/thread, channel-pair f32x2 ----------
// acc[p] packs output channels (2p, 2p+1). Weights in smem: sW[c][s][p] with
// w-pair (W[2p][c][s], W[2p+1][c][s]) so the inner loop is LDS.128 + 2 FFMA2.
__global__ __launch_bounds__(128) void k_conv(const int* __restrict__ gemm,
                                              const float* __restrict__ W,
                                              const float* __restrict__ bias,
                                              float* __restrict__ out, int E) {
    __shared__ __align__(16) unsigned long long sW[CIN * 5 * (COUT / 2)]; // [c][s][p]
    __shared__ float wsum[4][COUT];
    __shared__ float wsq[4][COUT];

    int t = threadIdx.x;
    for (int i = t; i < CIN * 5 * (COUT / 2); i += 128) {
        int c = i / (5 * 16);
        int r = i - c * (5 * 16);
        int s = r / 16;
        int p = r - s * 16;
        float w0 = W[((2 * p)     * CIN + c) * 5 + s];
        float w1 = W[((2 * p + 1) * CIN + c) * 5 + s];
        sW[i] = pack2(w0, w1);
    }
    __syncthreads();

    int b    = blockIdx.y;
    int e    = blockIdx.x * 128 + t;
    bool valid = e < E;
    int ec   = valid ? e : 0;
    int base = b * E;

    const int4* gv = (const int4*)gemm;
    int4 g = gv[base + ec];

    const float4* xt4 = (const float4*)g_xt;
    const float4* X  = xt4 + (size_t)(base + ec)  * 4;
    const float4* NA = xt4 + (size_t)(base + g.x) * 4;
    const float4* NB = xt4 + (size_t)(base + g.y) * 4;
    const float4* NC = xt4 + (size_t)(base + g.z) * 4;
    const float4* ND = xt4 + (size_t)(base + g.w) * 4;

    unsigned long long acc[COUT / 2];
#pragma unroll
    for (int p = 0; p < COUT / 2; p++)
        acc[p] = pack2(bias[2 * p], bias[2 * p + 1]);

#pragma unroll 1
    for (int q = 0; q < 4; q++) {
        float4 xv = X[q];
        float4 av = NA[q], bv = NB[q], cv = NC[q], dv = ND[q];
#pragma unroll
        for (int i = 0; i < 4; i++) {
            float aa = getc(av, i), cc = getc(cv, i);
            float bb = getc(bv, i), dd = getc(dv, i);
            unsigned long long f[5];
            {
                float xx = getc(xv, i);
                float t1 = fabsf(aa - cc);
                float t2 = aa + cc;
                float t3 = fabsf(bb - dd);
                float t4 = bb + dd;
                f[0] = pack2(xx, xx);
                f[1] = pack2(t1, t1);
                f[2] = pack2(t2, t2);
                f[3] = pack2(t3, t3);
                f[4] = pack2(t4, t4);
            }
            int c = q * 4 + i;
            const ulonglong2* Wc = (const ulonglong2*)(sW + c * 5 * 16);
#pragma unroll
            for (int s = 0; s < 5; s++) {
#pragma unroll
                for (int j = 0; j < 8; j++) {
                    ulonglong2 w = Wc[s * 8 + j];
                    acc[2 * j]     = ffma2(f[s], w.x, acc[2 * j]);
                    acc[2 * j + 1] = ffma2(f[s], w.y, acc[2 * j + 1]);
                }
            }
        }
    }

    // Write y (coalesced per channel) and per-thread channel stats.
    float ssum[COUT], ssq[COUT];
#pragma unroll
    for (int p = 0; p < COUT / 2; p++) {
        float lo, hi;
        unpack2(acc[p], lo, hi);
        if (valid) {
            out[((size_t)b * COUT + 2 * p)     * E + e] = lo;
            out[((size_t)b * COUT + 2 * p + 1) * E + e] = hi;
        }
        ssum[2 * p]     = valid ? lo : 0.0f;
        ssum[2 * p + 1] = valid ? hi : 0.0f;
        ssq[2 * p]      = valid ? lo * lo : 0.0f;
        ssq[2 * p + 1]  = valid ? hi * hi : 0.0f;
    }

    // Warp transpose-reduce: lane l ends holding warp total for channel l.
    int lane = t & 31, wid = t >> 5;
#pragma unroll
    for (int m = 16; m >= 1; m >>= 1) {
        bool up = (lane & m) != 0;
#pragma unroll
        for (int i = 0; i < m; i++) {
            float ks = up ? ssum[i + m] : ssum[i];
            float ds = up ? ssum[i] : ssum[i + m];
            ssum[i] = ks + __shfl_xor_sync(0xffffffffu, ds, m);
            float kq = up ? ssq[i + m] : ssq[i];
            float dq = up ? ssq[i] : ssq[i + m];
            ssq[i] = kq + __shfl_xor_sync(0xffffffffu, dq, m);
        }
    }
    wsum[wid][lane] = ssum[0];
    wsq[wid][lane]  = ssq[0];
    __syncthreads();
    if (t < COUT) {
        float S = 0.0f, Q = 0.0f;
#pragma unroll
        for (int w2 = 0; w2 < 4; w2++) { S += wsum[w2][t]; Q += wsq[w2][t]; }
        int blk = blockIdx.y * gridDim.x + blockIdx.x;
        g_psum[blk * COUT + t] = S;
        g_psq [blk * COUT + t] = Q;
    }
}

// ---------- Kernel C: finalize BN stats -> per-channel scale/shift ----------
__global__ __launch_bounds__(256) void k_stats(const float* __restrict__ gamma,
                                               const float* __restrict__ beta,
                                               int nb, float invN) {
    __shared__ float sS[256], sQ[256];
    int ch = blockIdx.x;
    int t  = threadIdx.x;
    float S = 0.0f, Q = 0.0f;
    for (int i = t; i < nb; i += 256) {
        S += g_psum[i * COUT + ch];
        Q += g_psq [i * COUT + ch];
    }
    sS[t] = S; sQ[t] = Q;
    __syncthreads();
    for (int h = 128; h > 0; h >>= 1) {
        if (t < h) { sS[t] += sS[t + h]; sQ[t] += sQ[t + h]; }
        __syncthreads();
    }
    if (t == 0) {
        float mean = sS[0] * invN;
        float var  = sQ[0] * invN - mean * mean;
        float sc   = gamma[ch] * rsqrtf(var + 1e-5f);
        g_scale[ch] = sc;
        g_shift[ch] = beta[ch] - mean * sc;
    }
}

// ---------- Kernel D: normalize + ReLU in place on d_out (2 float4/thread) ----------
__global__ __launch_bounds__(256) void k_norm(float* __restrict__ out, int E4) {
    int t   = threadIdx.x;
    int i0  = blockIdx.x * 512 + t;
    int i1  = i0 + 256;
    int bo  = blockIdx.y;              // b*COUT + o
    int ch  = bo & (COUT - 1);
    float s  = g_scale[ch];
    float sh = g_shift[ch];
    float4* base = (float4*)out + (size_t)bo * E4;
    bool v0 = i0 < E4, v1 = i1 < E4;
    float4 a, b2;
    if (v0) a  = base[i0];
    if (v1) b2 = base[i1];
    if (v0) {
        a.x = fmaxf(fmaf(a.x, s, sh), 0.0f);
        a.y = fmaxf(fmaf(a.y, s, sh), 0.0f);
        a.z = fmaxf(fmaf(a.z, s, sh), 0.0f);
        a.w = fmaxf(fmaf(a.w, s, sh), 0.0f);
        base[i0] = a;
    }
    if (v1) {
        b2.x = fmaxf(fmaf(b2.x, s, sh), 0.0f);
        b2.y = fmaxf(fmaf(b2.y, s, sh), 0.0f);
        b2.z = fmaxf(fmaf(b2.z, s, sh), 0.0f);
        b2.w = fmaxf(fmaf(b2.w, s, sh), 0.0f);
        base[i1] = b2;
    }
}

extern "C" void kernel_launch(void* const* d_in, const int* in_sizes, int n_in,
                              void* d_out, int out_size) {
    const float* x     = (const float*)d_in[0];
    const int*   gemm  = (const int*)  d_in[1];
    const float* W     = (const float*)d_in[2];
    const float* bias  = (const float*)d_in[3];
    const float* gamma = (const float*)d_in[4];
    const float* beta  = (const float*)d_in[5];
    float* out = (float*)d_out;

    int E  = in_sizes[0] / (BATCH * CIN);   // 120000
    int E4 = E >> 2;

    dim3 gA((unsigned)((E + 255) / 256), BATCH);
    k_transpose<<<gA, 256>>>(x, E);

    dim3 gB((unsigned)((E + 127) / 128), BATCH);
    k_conv<<<gB, 128>>>(gemm, W, bias, out, E);

    int nb = (int)(gB.x * gB.y);
    k_stats<<<COUT, 256>>>(gamma, beta, nb, 1.0f / ((float)BATCH * (float)E));

    dim3 gD((unsigned)((E4 + 511) / 512), BATCH * COUT);
    k_norm<<<gD, 256>>>(out, E4);
}

// round 3
// speedup vs baseline: 1.1002x; 1.0588x over previous
#include <cuda_runtime.h>

#define CIN   16
#define COUT  32
#define BATCH 8
#define MAXE  120000
#define MAXBLK 8192
#define TILE  128

// Scratch (static device globals; no allocation APIs).
__device__ float g_xt[(size_t)BATCH * MAXE * CIN];      // x transposed to [B][E][Cin]
__device__ float g_psum[MAXBLK * COUT];
__device__ float g_psq [MAXBLK * COUT];
__device__ float g_scale[COUT];
__device__ float g_shift[COUT];

// ---------- packed fp32x2 helpers (full fp32 precision per lane) ----------
__device__ __forceinline__ unsigned long long pack2(float lo, float hi) {
    unsigned long long r;
    asm("mov.b64 %0, {%1, %2};" : "=l"(r) : "f"(lo), "f"(hi));
    return r;
}
__device__ __forceinline__ void unpack2(unsigned long long v, float& lo, float& hi) {
    asm("mov.b64 {%0, %1}, %2;" : "=f"(lo), "=f"(hi) : "l"(v));
}
__device__ __forceinline__ unsigned long long ffma2(unsigned long long a,
                                                    unsigned long long b,
                                                    unsigned long long c) {
    unsigned long long d;
    asm("fma.rn.f32x2 %0, %1, %2, %3;" : "=l"(d) : "l"(a), "l"(b), "l"(c));
    return d;
}

__device__ __forceinline__ float getc(const float4& v, int i) {
    return i == 0 ? v.x : i == 1 ? v.y : i == 2 ? v.z : v.w;
}

// ---------- Kernel A: transpose x [B,Cin,E] -> g_xt [B,E,Cin] ----------
__global__ __launch_bounds__(256) void k_transpose(const float* __restrict__ x, int E) {
    __shared__ float tile[CIN][257];
    int b  = blockIdx.y;
    int t  = threadIdx.x;
    int e  = blockIdx.x * 256 + t;
    const float* xb = x + (size_t)b * CIN * E;
#pragma unroll
    for (int c = 0; c < CIN; c++)
        tile[c][t] = (e < E) ? xb[(size_t)c * E + e] : 0.0f;
    __syncthreads();
    if (e < E) {
        float4* dst = (float4*)(g_xt + ((size_t)b * E + e) * CIN);
#pragma unroll
        for (int q = 0; q < 4; q++)
            dst[q] = make_float4(tile[q * 4 + 0][t], tile[q * 4 + 1][t],
                                 tile[q * 4 + 2][t], tile[q * 4 + 3][t]);
    }
}

// ---------- Kernel B: mesh conv with cooperative staged gather ----------
// Phase 1: lane-quads gather each (edge,src) 64B row coalesced into smem.
// Phase 2: one edge/thread, channel-pair f32x2 accumulation (as R2).
__global__ __launch_bounds__(128) void k_conv(const int* __restrict__ gemm,
                                              const float* __restrict__ W,
                                              const float* __restrict__ bias,
                                              float* __restrict__ out, int E) {
    __shared__ __align__(16) unsigned long long sW[CIN * 5 * (COUT / 2)]; // [c][s][p] 10KB
    __shared__ float4 sF[4][4][TILE];   // [src-1][chunk q][edge] 32KB
    __shared__ int4  sG[TILE];          // neighbor ids, 2KB
    __shared__ float wsum[4][COUT];
    __shared__ float wsq[4][COUT];

    int t = threadIdx.x;
    for (int i = t; i < CIN * 5 * (COUT / 2); i += 128) {
        int c = i / (5 * 16);
        int r = i - c * (5 * 16);
        int s = r / 16;
        int p = r - s * 16;
        float w0 = W[((2 * p)     * CIN + c) * 5 + s];
        float w1 = W[((2 * p + 1) * CIN + c) * 5 + s];
        sW[i] = pack2(w0, w1);
    }

    int b    = blockIdx.y;
    int e0   = blockIdx.x * TILE;
    int e    = e0 + t;
    bool valid = e < E;
    int ec   = valid ? e : (E - 1);
    int base = b * E;

    const int4* gv = (const int4*)gemm;
    sG[t] = gv[base + ec];
    __syncthreads();

    // ---- Phase 1: cooperative gather of 4 neighbor rows per edge ----
    const float4* xt4 = (const float4*)g_xt;
    {
        int eL = t >> 2;          // local edge handled by this lane-quad (per rep)
        int q  = t & 3;           // 16B chunk within the 64B row
#pragma unroll
        for (int s = 0; s < 4; s++) {
#pragma unroll
            for (int rep = 0; rep < 4; rep++) {
                int el = rep * 32 + eL;                 // 0..127
                int nb = (&sG[el].x)[s];
                sF[s][q][el] = xt4[(size_t)(base + nb) * 4 + q];
            }
        }
    }
    __syncthreads();

    // ---- Phase 2: per-edge 80x32 contraction, f32x2 channel pairs ----
    const float4* X = xt4 + (size_t)(base + ec) * 4;

    unsigned long long acc[COUT / 2];
#pragma unroll
    for (int p = 0; p < COUT / 2; p++)
        acc[p] = pack2(bias[2 * p], bias[2 * p + 1]);

#pragma unroll 1
    for (int q = 0; q < 4; q++) {
        float4 xv = X[q];
        float4 av = sF[0][q][t];
        float4 bv = sF[1][q][t];
        float4 cv = sF[2][q][t];
        float4 dv = sF[3][q][t];
#pragma unroll
        for (int i = 0; i < 4; i++) {
            float aa = getc(av, i), cc = getc(cv, i);
            float bb = getc(bv, i), dd = getc(dv, i);
            unsigned long long f[5];
            {
                float xx = getc(xv, i);
                float t1 = fabsf(aa - cc);
                float t2 = aa + cc;
                float t3 = fabsf(bb - dd);
                float t4 = bb + dd;
                f[0] = pack2(xx, xx);
                f[1] = pack2(t1, t1);
                f[2] = pack2(t2, t2);
                f[3] = pack2(t3, t3);
                f[4] = pack2(t4, t4);
            }
            int c = q * 4 + i;
            const ulonglong2* Wc = (const ulonglong2*)(sW + c * 5 * 16);
#pragma unroll
            for (int s = 0; s < 5; s++) {
#pragma unroll
                for (int j = 0; j < 8; j++) {
                    ulonglong2 w = Wc[s * 8 + j];
                    acc[2 * j]     = ffma2(f[s], w.x, acc[2 * j]);
                    acc[2 * j + 1] = ffma2(f[s], w.y, acc[2 * j + 1]);
                }
            }
        }
    }

    // Write y (coalesced per channel) and per-thread channel stats.
    float ssum[COUT], ssq[COUT];
#pragma unroll
    for (int p = 0; p < COUT / 2; p++) {
        float lo, hi;
        unpack2(acc[p], lo, hi);
        if (valid) {
            out[((size_t)b * COUT + 2 * p)     * E + e] = lo;
            out[((size_t)b * COUT + 2 * p + 1) * E + e] = hi;
        }
        ssum[2 * p]     = valid ? lo : 0.0f;
        ssum[2 * p + 1] = valid ? hi : 0.0f;
        ssq[2 * p]      = valid ? lo * lo : 0.0f;
        ssq[2 * p + 1]  = valid ? hi * hi : 0.0f;
    }

    // Warp transpose-reduce: lane l ends holding warp total for channel l.
    int lane = t & 31, wid = t >> 5;
#pragma unroll
    for (int m = 16; m >= 1; m >>= 1) {
        bool up = (lane & m) != 0;
#pragma unroll
        for (int i = 0; i < m; i++) {
            float ks = up ? ssum[i + m] : ssum[i];
            float ds = up ? ssum[i] : ssum[i + m];
            ssum[i] = ks + __shfl_xor_sync(0xffffffffu, ds, m);
            float kq = up ? ssq[i + m] : ssq[i];
            float dq = up ? ssq[i] : ssq[i + m];
            ssq[i] = kq + __shfl_xor_sync(0xffffffffu, dq, m);
        }
    }
    wsum[wid][lane] = ssum[0];
    wsq[wid][lane]  = ssq[0];
    __syncthreads();
    if (t < COUT) {
        float S = 0.0f, Q = 0.0f;
#pragma unroll
        for (int w2 = 0; w2 < 4; w2++) { S += wsum[w2][t]; Q += wsq[w2][t]; }
        int blk = blockIdx.y * gridDim.x + blockIdx.x;
        g_psum[blk * COUT + t] = S;
        g_psq [blk * COUT + t] = Q;
    }
}

// ---------- Kernel C: finalize BN stats -> per-channel scale/shift ----------
__global__ __launch_bounds__(256) void k_stats(const float* __restrict__ gamma,
                                               const float* __restrict__ beta,
                                               int nb, float invN) {
    __shared__ float sS[256], sQ[256];
    int ch = blockIdx.x;
    int t  = threadIdx.x;
    float S = 0.0f, Q = 0.0f;
    for (int i = t; i < nb; i += 256) {
        S += g_psum[i * COUT + ch];
        Q += g_psq [i * COUT + ch];
    }
    sS[t] = S; sQ[t] = Q;
    __syncthreads();
    for (int h = 128; h > 0; h >>= 1) {
        if (t < h) { sS[t] += sS[t + h]; sQ[t] += sQ[t + h]; }
        __syncthreads();
    }
    if (t == 0) {
        float mean = sS[0] * invN;
        float var  = sQ[0] * invN - mean * mean;
        float sc   = gamma[ch] * rsqrtf(var + 1e-5f);
        g_scale[ch] = sc;
        g_shift[ch] = beta[ch] - mean * sc;
    }
}

// ---------- Kernel D: normalize + ReLU in place on d_out (2 float4/thread) ----------
__global__ __launch_bounds__(256) void k_norm(float* __restrict__ out, int E4) {
    int t   = threadIdx.x;
    int i0  = blockIdx.x * 512 + t;
    int i1  = i0 + 256;
    int bo  = blockIdx.y;              // b*COUT + o
    int ch  = bo & (COUT - 1);
    float s  = g_scale[ch];
    float sh = g_shift[ch];
    float4* base = (float4*)out + (size_t)bo * E4;
    bool v0 = i0 < E4, v1 = i1 < E4;
    float4 a, b2;
    if (v0) a  = base[i0];
    if (v1) b2 = base[i1];
    if (v0) {
        a.x = fmaxf(fmaf(a.x, s, sh), 0.0f);
        a.y = fmaxf(fmaf(a.y, s, sh), 0.0f);
        a.z = fmaxf(fmaf(a.z, s, sh), 0.0f);
        a.w = fmaxf(fmaf(a.w, s, sh), 0.0f);
        base[i0] = a;
    }
    if (v1) {
        b2.x = fmaxf(fmaf(b2.x, s, sh), 0.0f);
        b2.y = fmaxf(fmaf(b2.y, s, sh), 0.0f);
        b2.z = fmaxf(fmaf(b2.z, s, sh), 0.0f);
        b2.w = fmaxf(fmaf(b2.w, s, sh), 0.0f);
        base[i1] = b2;
    }
}

extern "C" void kernel_launch(void* const* d_in, const int* in_sizes, int n_in,
                              void* d_out, int out_size) {
    const float* x     = (const float*)d_in[0];
    const int*   gemm  = (const int*)  d_in[1];
    const float* W     = (const float*)d_in[2];
    const float* bias  = (const float*)d_in[3];
    const float* gamma = (const float*)d_in[4];
    const float* beta  = (const float*)d_in[5];
    float* out = (float*)d_out;

    int E  = in_sizes[0] / (BATCH * CIN);   // 120000
    int E4 = E >> 2;

    dim3 gA((unsigned)((E + 255) / 256), BATCH);
    k_transpose<<<gA, 256>>>(x, E);

    dim3 gB((unsigned)((E + TILE - 1) / TILE), BATCH);
    k_conv<<<gB, TILE>>>(gemm, W, bias, out, E);

    int nb = (int)(gB.x * gB.y);
    k_stats<<<COUT, 256>>>(gamma, beta, nb, 1.0f / ((float)BATCH * (float)E));

    dim3 gD((unsigned)((E4 + 511) / 512), BATCH * COUT);
    k_norm<<<gD, 256>>>(out, E4);
}

// round 5
// speedup vs baseline: 1.2424x; 1.1292x over previous
#include <cuda_runtime.h>

#define CIN   16
#define COUT  32
#define BATCH 8
#define MAXBLK 8192
#define TILE  256          // edges per conv block
#define THR   128          // threads per conv block
#define FPITCH 260         // feat row pitch (floats): 256 + pad (16B-aligned, conflict-free)

// Scratch (static device globals; no allocation APIs).
__device__ float g_xt[(size_t)BATCH * 120000 * CIN];  // x transposed to [B][E][Cin]
__device__ float g_psum[MAXBLK * COUT];
__device__ float g_psq [MAXBLK * COUT];
__device__ float g_scale[COUT];
__device__ float g_shift[COUT];

// ---------- packed fp32x2 helpers (full fp32 precision per lane) ----------
__device__ __forceinline__ unsigned long long pack2(float lo, float hi) {
    unsigned long long r;
    asm("mov.b64 %0, {%1, %2};" : "=l"(r) : "f"(lo), "f"(hi));
    return r;
}
__device__ __forceinline__ void unpack2(unsigned long long v, float& lo, float& hi) {
    asm("mov.b64 {%0, %1}, %2;" : "=f"(lo), "=f"(hi) : "l"(v));
}
__device__ __forceinline__ unsigned long long ffma2(unsigned long long a,
                                                    unsigned long long b,
                                                    unsigned long long c) {
    unsigned long long d;
    asm("fma.rn.f32x2 %0, %1, %2, %3;" : "=l"(d) : "l"(a), "l"(b), "l"(c));
    return d;
}
__device__ __forceinline__ float getc(const float4& v, int i) {
    return i == 0 ? v.x : i == 1 ? v.y : i == 2 ? v.z : v.w;
}

// ---------- Kernel A: transpose x [B,Cin,E] -> g_xt [B,E,Cin] ----------
__global__ __launch_bounds__(256) void k_transpose(const float* __restrict__ x, int E) {
    __shared__ float tile[CIN][257];
    int b  = blockIdx.y;
    int t  = threadIdx.x;
    int e  = blockIdx.x * 256 + t;
    const float* xb = x + (size_t)b * CIN * E;
#pragma unroll
    for (int c = 0; c < CIN; c++)
        tile[c][t] = (e < E) ? xb[(size_t)c * E + e] : 0.0f;
    __syncthreads();
    if (e < E) {
        float4* dst = (float4*)(g_xt + ((size_t)b * E + e) * CIN);
#pragma unroll
        for (int q = 0; q < 4; q++)
            dst[q] = make_float4(tile[q * 4 + 0][t], tile[q * 4 + 1][t],
                                 tile[q * 4 + 2][t], tile[q * 4 + 3][t]);
    }
}

// ---------- Kernel B: mesh conv as staged-feature GEMM ----------
// Phase 1: cooperative gather (lane-quad per (edge,chunk)) builds the 80
//          per-edge features directly into smem feat[k][e].
// Phase 2: register-tiled GEMM: thread = 4 edges x 16 channels (8 f32x2 pairs).
__global__ __launch_bounds__(THR) void k_conv(const int* __restrict__ gemm,
                                              const float* __restrict__ W,
                                              const float* __restrict__ bias,
                                              float* __restrict__ out, int E) {
    extern __shared__ float dsm[];
    float* feat = dsm;                                          // 80*FPITCH floats
    unsigned long long* sW2 = (unsigned long long*)(dsm + 80 * FPITCH);  // [80][16] u64
    int4*  sG   = (int4*)(dsm + 80 * FPITCH + 2560);            // 256 int4
    float* wsum = dsm + 80 * FPITCH + 2560 + 1024;              // [4][32]
    float* wsq  = wsum + 128;

    int t    = threadIdx.x;
    int b    = blockIdx.y;
    int e0   = blockIdx.x * TILE;
    int base = b * E;

    // Weights: sW2[k*16 + p] = (W[2p][k], W[2p+1][k]) with k = c*5+s, W row-major [o][c][s]
    for (int i = t; i < 80 * 16; i += THR) {
        int k = i >> 4, p = i & 15;
        sW2[i] = pack2(W[(2 * p) * 80 + k], W[(2 * p + 1) * 80 + k]);
    }
    // Neighbor ids
    const int4* gv = (const int4*)gemm;
#pragma unroll
    for (int j = 0; j < 2; j++) {
        int el = t + j * THR;
        int e  = e0 + el;
        sG[el] = gv[base + (e < E ? e : E - 1)];
    }
    __syncthreads();

    // ---- Phase 1: gather + feature build ----
    const float4* xt4 = (const float4*)g_xt;
#pragma unroll
    for (int j = 0; j < 8; j++) {
        int idx = t + j * THR;          // 0..1023
        int el  = idx >> 2;
        int q   = idx & 3;
        int4 g  = sG[el];
        int e   = e0 + el;
        int ecl = e < E ? e : E - 1;
        float4 xv = xt4[(size_t)(base + ecl) * 4 + q];
        float4 av = xt4[(size_t)(base + g.x) * 4 + q];
        float4 bv = xt4[(size_t)(base + g.y) * 4 + q];
        float4 cv = xt4[(size_t)(base + g.z) * 4 + q];
        float4 dv = xt4[(size_t)(base + g.w) * 4 + q];
#pragma unroll
        for (int i = 0; i < 4; i++) {
            int k0 = (4 * q + i) * 5;
            float aa = getc(av, i), cc = getc(cv, i);
            float bb = getc(bv, i), dd = getc(dv, i);
            feat[(k0 + 0) * FPITCH + el] = getc(xv, i);
            feat[(k0 + 1) * FPITCH + el] = fabsf(aa - cc);
            feat[(k0 + 2) * FPITCH + el] = aa + cc;
            feat[(k0 + 3) * FPITCH + el] = fabsf(bb - dd);
            feat[(k0 + 4) * FPITCH + el] = bb + dd;
        }
    }
    __syncthreads();

    // ---- Phase 2: register-tiled GEMM ----
    int h  = t >> 6;        // channel half (0: ch 0-15, 1: ch 16-31)
    int g2 = t & 63;        // edge group: edges 4*g2 .. 4*g2+3

    unsigned long long acc[4][8];
#pragma unroll
    for (int p = 0; p < 8; p++) {
        unsigned long long bi = pack2(bias[h * 16 + 2 * p], bias[h * 16 + 2 * p + 1]);
#pragma unroll
        for (int e = 0; e < 4; e++) acc[e][p] = bi;
    }

    const ulonglong2* wrow = (const ulonglong2*)(sW2 + h * 8);
    const float* frow = feat + 4 * g2;

#pragma unroll 2
    for (int k = 0; k < 80; k++) {
        float4 fv = *(const float4*)(frow + k * FPITCH);
        unsigned long long f0 = pack2(fv.x, fv.x);
        unsigned long long f1 = pack2(fv.y, fv.y);
        unsigned long long f2 = pack2(fv.z, fv.z);
        unsigned long long f3 = pack2(fv.w, fv.w);
        ulonglong2 wa = wrow[k * 8 + 0];
        ulonglong2 wb = wrow[k * 8 + 1];
        ulonglong2 wc = wrow[k * 8 + 2];
        ulonglong2 wd = wrow[k * 8 + 3];
        unsigned long long w[8] = {wa.x, wa.y, wb.x, wb.y, wc.x, wc.y, wd.x, wd.y};
#pragma unroll
        for (int p = 0; p < 8; p++) {
            acc[0][p] = ffma2(f0, w[p], acc[0][p]);
            acc[1][p] = ffma2(f1, w[p], acc[1][p]);
            acc[2][p] = ffma2(f2, w[p], acc[2][p]);
            acc[3][p] = ffma2(f3, w[p], acc[3][p]);
        }
    }

    // ---- Epilogue: stores + per-thread stats ----
    float ssum[16], ssq[16];
#pragma unroll
    for (int i = 0; i < 16; i++) { ssum[i] = 0.0f; ssq[i] = 0.0f; }

    int ebase = e0 + 4 * g2;
#pragma unroll
    for (int e = 0; e < 4; e++) {
        int ge = ebase + e;
        bool v = ge < E;
#pragma unroll
        for (int p = 0; p < 8; p++) {
            float lo, hi;
            unpack2(acc[e][p], lo, hi);
            int ch = h * 16 + 2 * p;
            if (v) {
                out[((size_t)b * COUT + ch)     * E + ge] = lo;
                out[((size_t)b * COUT + ch + 1) * E + ge] = hi;
                ssum[2 * p]     += lo;
                ssum[2 * p + 1] += hi;
                ssq[2 * p]      += lo * lo;
                ssq[2 * p + 1]  += hi * hi;
            }
        }
    }

    // Fold upper 16 lanes onto lower 16, then 16-wide transpose-reduce.
    int lane = t & 31, wid = t >> 5;
#pragma unroll
    for (int i = 0; i < 16; i++) {
        ssum[i] += __shfl_xor_sync(0xffffffffu, ssum[i], 16);
        ssq[i]  += __shfl_xor_sync(0xffffffffu, ssq[i], 16);
    }
    int lane16 = lane & 15;
#pragma unroll
    for (int m = 8; m >= 1; m >>= 1) {
        bool up = (lane16 & m) != 0;
#pragma unroll
        for (int i = 0; i < m; i++) {
            float ks = up ? ssum[i + m] : ssum[i];
            float ds = up ? ssum[i] : ssum[i + m];
            ssum[i] = ks + __shfl_xor_sync(0xffffffffu, ds, m);
            float kq = up ? ssq[i + m] : ssq[i];
            float dq = up ? ssq[i] : ssq[i + m];
            ssq[i] = kq + __shfl_xor_sync(0xffffffffu, dq, m);
        }
    }
    if (lane < 16) {
        wsum[wid * 32 + h * 16 + lane16] = ssum[0];
        wsq [wid * 32 + h * 16 + lane16] = ssq[0];
    }
    __syncthreads();
    if (t < COUT) {
        int hh = t >> 4;                 // which half this channel belongs to
        float S = wsum[(2 * hh) * 32 + t] + wsum[(2 * hh + 1) * 32 + t];
        float Q = wsq [(2 * hh) * 32 + t] + wsq [(2 * hh + 1) * 32 + t];
        int blk = blockIdx.y * gridDim.x + blockIdx.x;
        g_psum[blk * COUT + t] = S;
        g_psq [blk * COUT + t] = Q;
    }
}

// ---------- Kernel C: finalize BN stats -> per-channel scale/shift ----------
__global__ __launch_bounds__(256) void k_stats(const float* __restrict__ gamma,
                                               const float* __restrict__ beta,
                                               int nb, float invN) {
    __shared__ float sS[256], sQ[256];
    int ch = blockIdx.x;
    int t  = threadIdx.x;
    float S = 0.0f, Q = 0.0f;
    for (int i = t; i < nb; i += 256) {
        S += g_psum[i * COUT + ch];
        Q += g_psq [i * COUT + ch];
    }
    sS[t] = S; sQ[t] = Q;
    __syncthreads();
    for (int h = 128; h > 0; h >>= 1) {
        if (t < h) { sS[t] += sS[t + h]; sQ[t] += sQ[t + h]; }
        __syncthreads();
    }
    if (t == 0) {
        float mean = sS[0] * invN;
        float var  = sQ[0] * invN - mean * mean;
        float sc   = gamma[ch] * rsqrtf(var + 1e-5f);
        g_scale[ch] = sc;
        g_shift[ch] = beta[ch] - mean * sc;
    }
}

// ---------- Kernel D: normalize + ReLU in place on d_out (2 float4/thread) ----------
__global__ __launch_bounds__(256) void k_norm(float* __restrict__ out, int E4) {
    int t   = threadIdx.x;
    int i0  = blockIdx.x * 512 + t;
    int i1  = i0 + 256;
    int bo  = blockIdx.y;              // b*COUT + o
    int ch  = bo & (COUT - 1);
    float s  = g_scale[ch];
    float sh = g_shift[ch];
    float4* base = (float4*)out + (size_t)bo * E4;
    bool v0 = i0 < E4, v1 = i1 < E4;
    float4 a, b2;
    if (v0) a  = base[i0];
    if (v1) b2 = base[i1];
    if (v0) {
        a.x = fmaxf(fmaf(a.x, s, sh), 0.0f);
        a.y = fmaxf(fmaf(a.y, s, sh), 0.0f);
        a.z = fmaxf(fmaf(a.z, s, sh), 0.0f);
        a.w = fmaxf(fmaf(a.w, s, sh), 0.0f);
        base[i0] = a;
    }
    if (v1) {
        b2.x = fmaxf(fmaf(b2.x, s, sh), 0.0f);
        b2.y = fmaxf(fmaf(b2.y, s, sh), 0.0f);
        b2.z = fmaxf(fmaf(b2.z, s, sh), 0.0f);
        b2.w = fmaxf(fmaf(b2.w, s, sh), 0.0f);
        base[i1] = b2;
    }
}

extern "C" void kernel_launch(void* const* d_in, const int* in_sizes, int n_in,
                              void* d_out, int out_size) {
    const float* x     = (const float*)d_in[0];
    const int*   gemm  = (const int*)  d_in[1];
    const float* W     = (const float*)d_in[2];
    const float* bias  = (const float*)d_in[3];
    const float* gamma = (const float*)d_in[4];
    const float* beta  = (const float*)d_in[5];
    float* out = (float*)d_out;

    int E  = in_sizes[0] / (BATCH * CIN);   // 120000
    int E4 = E >> 2;

    dim3 gA((unsigned)((E + 255) / 256), BATCH);
    k_transpose<<<gA, 256>>>(x, E);

    int convSmem = (80 * FPITCH + 2560 + 1024 + 256) * 4;  // ~98.6 KB
    cudaFuncSetAttribute(k_conv, cudaFuncAttributeMaxDynamicSharedMemorySize, convSmem);
    dim3 gB((unsigned)((E + TILE - 1) / TILE), BATCH);
    k_conv<<<gB, THR, convSmem>>>(gemm, W, bias, out, E);

    int nb = (int)(gB.x * gB.y);
    k_stats<<<COUT, 256>>>(gamma, beta, nb, 1.0f / ((float)BATCH * (float)E));

    dim3 gD((unsigned)((E4 + 511) / 512), BATCH * COUT);
    k_norm<<<gD, 256>>>(out, E4);
}

// round 6
// speedup vs baseline: 1.3184x; 1.0612x over previous
#include <cuda_runtime.h>

#define CIN   16
#define COUT  32
#define BATCH 8
#define MAXBLK 8192
#define TILE  128          // edges per conv block
#define THR   128          // threads per conv block
#define FPITCH 132         // feat row pitch (floats)

// Scratch (static device globals; no allocation APIs).
__device__ float g_xt[(size_t)BATCH * 120000 * CIN];  // x transposed to [B][E][Cin]
__device__ float g_psum[MAXBLK * COUT];
__device__ float g_psq [MAXBLK * COUT];
__device__ float g_scale[COUT];
__device__ float g_shift[COUT];

// ---------- packed fp32x2 helpers (full fp32 precision per lane) ----------
__device__ __forceinline__ unsigned long long pack2(float lo, float hi) {
    unsigned long long r;
    asm("mov.b64 %0, {%1, %2};" : "=l"(r) : "f"(lo), "f"(hi));
    return r;
}
__device__ __forceinline__ void unpack2(unsigned long long v, float& lo, float& hi) {
    asm("mov.b64 {%0, %1}, %2;" : "=f"(lo), "=f"(hi) : "l"(v));
}
__device__ __forceinline__ unsigned long long ffma2(unsigned long long a,
                                                    unsigned long long b,
                                                    unsigned long long c) {
    unsigned long long d;
    asm("fma.rn.f32x2 %0, %1, %2, %3;" : "=l"(d) : "l"(a), "l"(b), "l"(c));
    return d;
}
__device__ __forceinline__ float getc(const float4& v, int i) {
    return i == 0 ? v.x : i == 1 ? v.y : i == 2 ? v.z : v.w;
}

// ---------- Kernel A: transpose x [B,Cin,E] -> g_xt [B,E,Cin] ----------
__global__ __launch_bounds__(256) void k_transpose(const float* __restrict__ x, int E) {
    __shared__ float tile[CIN][257];
    int b  = blockIdx.y;
    int t  = threadIdx.x;
    int e  = blockIdx.x * 256 + t;
    const float* xb = x + (size_t)b * CIN * E;
#pragma unroll
    for (int c = 0; c < CIN; c++)
        tile[c][t] = (e < E) ? xb[(size_t)c * E + e] : 0.0f;
    __syncthreads();
    if (e < E) {
        float4* dst = (float4*)(g_xt + ((size_t)b * E + e) * CIN);
#pragma unroll
        for (int q = 0; q < 4; q++)
            dst[q] = make_float4(tile[q * 4 + 0][t], tile[q * 4 + 1][t],
                                 tile[q * 4 + 2][t], tile[q * 4 + 3][t]);
    }
}

// ---------- Kernel B: mesh conv as staged-feature GEMM ----------
// Phase 1: cooperative gather builds 80 per-edge features into smem feat[k][e].
// Phase 2: register-tiled GEMM: thread = 2 edges x 16 channels (8 f32x2 pairs x 2).
// Small tile (54KB smem) -> 4 blocks/SM for latency hiding.
__global__ __launch_bounds__(THR) void k_conv(const int* __restrict__ gemm,
                                              const float* __restrict__ W,
                                              const float* __restrict__ bias,
                                              float* __restrict__ out, int E) {
    extern __shared__ float dsm[];
    float* feat = dsm;                                          // 80*FPITCH floats
    unsigned long long* sW2 = (unsigned long long*)(dsm + 80 * FPITCH);  // [80][16] u64
    int4*  sG   = (int4*)(dsm + 80 * FPITCH + 2560);            // 128 int4
    float* wsum = dsm + 80 * FPITCH + 2560 + 512;               // [4][32]
    float* wsq  = wsum + 128;

    int t    = threadIdx.x;
    int b    = blockIdx.y;
    int e0   = blockIdx.x * TILE;
    int base = b * E;

    // Weights: sW2[k*16 + p] = (W[2p][k], W[2p+1][k]) with k = c*5+s, W row-major [o][c][s]
    for (int i = t; i < 80 * 16; i += THR) {
        int k = i >> 4, p = i & 15;
        sW2[i] = pack2(W[(2 * p) * 80 + k], W[(2 * p + 1) * 80 + k]);
    }
    // Neighbor ids
    const int4* gv = (const int4*)gemm;
    {
        int e = e0 + t;
        sG[t] = gv[base + (e < E ? e : E - 1)];
    }
    __syncthreads();

    // ---- Phase 1: gather + feature build ----
    const float4* xt4 = (const float4*)g_xt;
#pragma unroll
    for (int j = 0; j < 4; j++) {
        int idx = t + j * THR;          // 0..511
        int el  = idx >> 2;
        int q   = idx & 3;
        int4 g  = sG[el];
        int e   = e0 + el;
        int ecl = e < E ? e : E - 1;
        float4 xv = xt4[(size_t)(base + ecl) * 4 + q];
        float4 av = xt4[(size_t)(base + g.x) * 4 + q];
        float4 bv = xt4[(size_t)(base + g.y) * 4 + q];
        float4 cv = xt4[(size_t)(base + g.z) * 4 + q];
        float4 dv = xt4[(size_t)(base + g.w) * 4 + q];
#pragma unroll
        for (int i = 0; i < 4; i++) {
            int k0 = (4 * q + i) * 5;
            float aa = getc(av, i), cc = getc(cv, i);
            float bb = getc(bv, i), dd = getc(dv, i);
            feat[(k0 + 0) * FPITCH + el] = getc(xv, i);
            feat[(k0 + 1) * FPITCH + el] = fabsf(aa - cc);
            feat[(k0 + 2) * FPITCH + el] = aa + cc;
            feat[(k0 + 3) * FPITCH + el] = fabsf(bb - dd);
            feat[(k0 + 4) * FPITCH + el] = bb + dd;
        }
    }
    __syncthreads();

    // ---- Phase 2: register-tiled GEMM ----
    int h  = t >> 6;        // channel half (0: ch 0-15, 1: ch 16-31)
    int g2 = t & 63;        // edge pair: edges 2*g2, 2*g2+1

    unsigned long long acc[2][8];
#pragma unroll
    for (int p = 0; p < 8; p++) {
        unsigned long long bi = pack2(bias[h * 16 + 2 * p], bias[h * 16 + 2 * p + 1]);
        acc[0][p] = bi;
        acc[1][p] = bi;
    }

    const ulonglong2* wrow = (const ulonglong2*)(sW2 + h * 8);
    const float* frow = feat + 2 * g2;

#pragma unroll 4
    for (int k = 0; k < 80; k++) {
        float2 fv = *(const float2*)(frow + k * FPITCH);
        unsigned long long f0 = pack2(fv.x, fv.x);
        unsigned long long f1 = pack2(fv.y, fv.y);
        ulonglong2 wa = wrow[k * 8 + 0];
        ulonglong2 wb = wrow[k * 8 + 1];
        ulonglong2 wc = wrow[k * 8 + 2];
        ulonglong2 wd = wrow[k * 8 + 3];
        unsigned long long w[8] = {wa.x, wa.y, wb.x, wb.y, wc.x, wc.y, wd.x, wd.y};
#pragma unroll
        for (int p = 0; p < 8; p++) {
            acc[0][p] = ffma2(f0, w[p], acc[0][p]);
            acc[1][p] = ffma2(f1, w[p], acc[1][p]);
        }
    }

    // ---- Epilogue: stores + per-thread stats ----
    float ssum[16], ssq[16];
#pragma unroll
    for (int i = 0; i < 16; i++) { ssum[i] = 0.0f; ssq[i] = 0.0f; }

    int ebase = e0 + 2 * g2;
#pragma unroll
    for (int e = 0; e < 2; e++) {
        int ge = ebase + e;
        bool v = ge < E;
#pragma unroll
        for (int p = 0; p < 8; p++) {
            float lo, hi;
            unpack2(acc[e][p], lo, hi);
            int ch = h * 16 + 2 * p;
            if (v) {
                out[((size_t)b * COUT + ch)     * E + ge] = lo;
                out[((size_t)b * COUT + ch + 1) * E + ge] = hi;
                ssum[2 * p]     += lo;
                ssum[2 * p + 1] += hi;
                ssq[2 * p]      += lo * lo;
                ssq[2 * p + 1]  += hi * hi;
            }
        }
    }

    // Fold upper 16 lanes onto lower 16, then 16-wide transpose-reduce.
    int lane = t & 31, wid = t >> 5;
#pragma unroll
    for (int i = 0; i < 16; i++) {
        ssum[i] += __shfl_xor_sync(0xffffffffu, ssum[i], 16);
        ssq[i]  += __shfl_xor_sync(0xffffffffu, ssq[i], 16);
    }
    int lane16 = lane & 15;
#pragma unroll
    for (int m = 8; m >= 1; m >>= 1) {
        bool up = (lane16 & m) != 0;
#pragma unroll
        for (int i = 0; i < m; i++) {
            float ks = up ? ssum[i + m] : ssum[i];
            float ds = up ? ssum[i] : ssum[i + m];
            ssum[i] = ks + __shfl_xor_sync(0xffffffffu, ds, m);
            float kq = up ? ssq[i + m] : ssq[i];
            float dq = up ? ssq[i] : ssq[i + m];
            ssq[i] = kq + __shfl_xor_sync(0xffffffffu, dq, m);
        }
    }
    if (lane < 16) {
        wsum[wid * 32 + h * 16 + lane16] = ssum[0];
        wsq [wid * 32 + h * 16 + lane16] = ssq[0];
    }
    __syncthreads();
    if (t < COUT) {
        int hh = t >> 4;                 // which half this channel belongs to
        float S = wsum[(2 * hh) * 32 + t] + wsum[(2 * hh + 1) * 32 + t];
        float Q = wsq [(2 * hh) * 32 + t] + wsq [(2 * hh + 1) * 32 + t];
        int blk = blockIdx.y * gridDim.x + blockIdx.x;
        g_psum[blk * COUT + t] = S;
        g_psq [blk * COUT + t] = Q;
    }
}

// ---------- Kernel C: finalize BN stats -> per-channel scale/shift ----------
__global__ __launch_bounds__(256) void k_stats(const float* __restrict__ gamma,
                                               const float* __restrict__ beta,
                                               int nb, float invN) {
    __shared__ float sS[256], sQ[256];
    int ch = blockIdx.x;
    int t  = threadIdx.x;
    float S = 0.0f, Q = 0.0f;
    for (int i = t; i < nb; i += 256) {
        S += g_psum[i * COUT + ch];
        Q += g_psq [i * COUT + ch];
    }
    sS[t] = S; sQ[t] = Q;
    __syncthreads();
    for (int h = 128; h > 0; h >>= 1) {
        if (t < h) { sS[t] += sS[t + h]; sQ[t] += sQ[t + h]; }
        __syncthreads();
    }
    if (t == 0) {
        float mean = sS[0] * invN;
        float var  = sQ[0] * invN - mean * mean;
        float sc   = gamma[ch] * rsqrtf(var + 1e-5f);
        g_scale[ch] = sc;
        g_shift[ch] = beta[ch] - mean * sc;
    }
}

// ---------- Kernel D: normalize + ReLU in place on d_out (2 float4/thread) ----------
__global__ __launch_bounds__(256) void k_norm(float* __restrict__ out, int E4) {
    int t   = threadIdx.x;
    int i0  = blockIdx.x * 512 + t;
    int i1  = i0 + 256;
    int bo  = blockIdx.y;              // b*COUT + o
    int ch  = bo & (COUT - 1);
    float s  = g_scale[ch];
    float sh = g_shift[ch];
    float4* base = (float4*)out + (size_t)bo * E4;
    bool v0 = i0 < E4, v1 = i1 < E4;
    float4 a, b2;
    if (v0) a  = base[i0];
    if (v1) b2 = base[i1];
    if (v0) {
        a.x = fmaxf(fmaf(a.x, s, sh), 0.0f);
        a.y = fmaxf(fmaf(a.y, s, sh), 0.0f);
        a.z = fmaxf(fmaf(a.z, s, sh), 0.0f);
        a.w = fmaxf(fmaf(a.w, s, sh), 0.0f);
        base[i0] = a;
    }
    if (v1) {
        b2.x = fmaxf(fmaf(b2.x, s, sh), 0.0f);
        b2.y = fmaxf(fmaf(b2.y, s, sh), 0.0f);
        b2.z = fmaxf(fmaf(b2.z, s, sh), 0.0f);
        b2.w = fmaxf(fmaf(b2.w, s, sh), 0.0f);
        base[i1] = b2;
    }
}

extern "C" void kernel_launch(void* const* d_in, const int* in_sizes, int n_in,
                              void* d_out, int out_size) {
    const float* x     = (const float*)d_in[0];
    const int*   gemm  = (const int*)  d_in[1];
    const float* W     = (const float*)d_in[2];
    const float* bias  = (const float*)d_in[3];
    const float* gamma = (const float*)d_in[4];
    const float* beta  = (const float*)d_in[5];
    float* out = (float*)d_out;

    int E  = in_sizes[0] / (BATCH * CIN);   // 120000
    int E4 = E >> 2;

    dim3 gA((unsigned)((E + 255) / 256), BATCH);
    k_transpose<<<gA, 256>>>(x, E);

    int convSmem = (80 * FPITCH + 2560 + 512 + 256) * 4;  // 55552 B (~54.3 KB)
    cudaFuncSetAttribute(k_conv, cudaFuncAttributeMaxDynamicSharedMemorySize, convSmem);
    dim3 gB((unsigned)((E + TILE - 1) / TILE), BATCH);
    k_conv<<<gB, THR, convSmem>>>(gemm, W, bias, out, E);

    int nb = (int)(gB.x * gB.y);
    k_stats<<<COUT, 256>>>(gamma, beta, nb, 1.0f / ((float)BATCH * (float)E));

    dim3 gD((unsigned)((E4 + 511) / 512), BATCH * COUT);
    k_norm<<<gD, 256>>>(out, E4);
}